// round 2
// baseline (speedup 1.0000x reference)
#include <cuda_runtime.h>

// Problem constants (all powers of two)
#define NN   2
#define CC   16
#define DHW  (32 * 128 * 128)       // 524288 = 2^19
#define MV   (NN * DHW)             // 1048576 voxels = 2^20
#define LOG2_DHW 19

__device__ double g_sum;            // sum of log2 terms
__device__ int    g_cnt;            // number of valid voxels

__global__ void ord_init_kernel() {
    g_sum = 0.0;
    g_cnt = 0;
}

__global__ __launch_bounds__(256) void ord_main_kernel(
    const float* __restrict__ pred,
    const int*   __restrict__ target,
    const int*   __restrict__ mask)
{
    const int g  = blockIdx.x * blockDim.x + threadIdx.x;  // 4-voxel group id
    const int v4 = g << 2;                                 // first voxel in group
    const int n  = v4 >> LOG2_DHW;                         // batch index
    const int v  = v4 & (DHW - 1);                         // index within DHW

    const size_t nbase = (size_t)n * CC * DHW;             // start of batch n in pred/target

    const int4 m4 = *reinterpret_cast<const int4*>(mask + (size_t)n * DHW + v);
    const int4 t4 = *reinterpret_cast<const int4*>(target + nbase + v); // channel 0 (broadcast)

    const bool va = m4.x > 0;
    const bool vb = m4.y > 0;
    const bool vc = m4.z > 0;
    const bool vd = m4.w > 0;

    int cnt = (int)va + (int)vb + (int)vc + (int)vd;

    const float* pbase = pred + nbase + v;

    float s = 0.0f;
    #pragma unroll
    for (int c = 0; c < CC; c++) {
        const float4 p = *reinterpret_cast<const float4*>(pbase + (size_t)c * DHW);

        float xa = (c <= t4.x) ? p.x : 1.0f - p.x;
        float xb = (c <= t4.y) ? p.y : 1.0f - p.y;
        float xc = (c <= t4.z) ? p.z : 1.0f - p.z;
        float xd = (c <= t4.w) ? p.w : 1.0f - p.w;

        xa = fminf(fmaxf(xa, 1e-8f), 1e8f);
        xb = fminf(fmaxf(xb, 1e-8f), 1e8f);
        xc = fminf(fmaxf(xc, 1e-8f), 1e8f);
        xd = fminf(fmaxf(xd, 1e-8f), 1e8f);

        // accumulate log2; multiply by ln(2) once at the very end
        s += va ? __log2f(xa) : 0.0f;
        s += vb ? __log2f(xb) : 0.0f;
        s += vc ? __log2f(xc) : 0.0f;
        s += vd ? __log2f(xd) : 0.0f;
    }

    // warp reduction
    #pragma unroll
    for (int off = 16; off > 0; off >>= 1) {
        s   += __shfl_xor_sync(0xffffffffu, s, off);
        cnt += __shfl_xor_sync(0xffffffffu, cnt, off);
    }

    __shared__ float sh_s[8];
    __shared__ int   sh_c[8];
    const int wid = threadIdx.x >> 5;
    const int lid = threadIdx.x & 31;
    if (lid == 0) { sh_s[wid] = s; sh_c[wid] = cnt; }
    __syncthreads();

    if (threadIdx.x == 0) {
        float bs = 0.0f;
        int   bc = 0;
        #pragma unroll
        for (int i = 0; i < 8; i++) { bs += sh_s[i]; bc += sh_c[i]; }
        atomicAdd(&g_sum, (double)bs);
        atomicAdd(&g_cnt, bc);
    }
}

__global__ void ord_final_kernel(float* __restrict__ out) {
    // s_ln = g_sum * ln(2);  result = s_ln / (-S)
    const double LN2 = 0.69314718055994530942;
    out[0] = (float)((g_sum * LN2) / (-(double)g_cnt));
}

extern "C" void kernel_launch(void* const* d_in, const int* in_sizes, int n_in,
                              void* d_out, int out_size)
{
    const float* pred   = (const float*)d_in[0];
    const int*   target = (const int*)d_in[1];
    const int*   mask   = (const int*)d_in[2];
    float*       out    = (float*)d_out;

    ord_init_kernel<<<1, 1>>>();

    const int threads = 256;
    const int groups  = MV / 4;                 // 262144 threads
    const int blocks  = groups / threads;       // 1024 blocks
    ord_main_kernel<<<blocks, threads>>>(pred, target, mask);

    ord_final_kernel<<<1, 1>>>(out);
}